// round 2
// baseline (speedup 1.0000x reference)
#include <cuda_runtime.h>
#include <math_constants.h>

#define S_LEN  4096
#define BATCH  4
#define DMODEL 512
#define DHEAD  64
#define BM     64
#define BN     64
#define NROWS  (BATCH * S_LEN)

// Scratch for projected Q/K/V (allocation-free rule: __device__ globals)
__device__ float g_q[NROWS * DHEAD];
__device__ float g_k[NROWS * DHEAD];
__device__ float g_v[NROWS * DHEAD];

// ---------------------------------------------------------------------------
// QKV projection: out[row][col] = (sum_k x[row][k] * W[k][col] + b[col]) * scale
// Tile 64 rows x 64 cols, K chunks of 32. blockIdx.y selects Q/K/V.
// Q gets the 1/sqrt(DHEAD) = 0.125 softmax scale folded in.
// ---------------------------------------------------------------------------
__global__ __launch_bounds__(256)
void qkv_kernel(const float* __restrict__ x,
                const float* __restrict__ Wq, const float* __restrict__ bq,
                const float* __restrict__ Wk, const float* __restrict__ bk,
                const float* __restrict__ Wv, const float* __restrict__ bv) {
    __shared__ float Xt[32][BM];     // [k][m] transposed for float4 reads over m
    __shared__ float Ws[32][DHEAD];  // [k][n]

    const float* W; const float* bias; float* out; float scale;
    switch (blockIdx.y) {
        case 0:  W = Wq; bias = bq; out = g_q; scale = 0.125f; break;
        case 1:  W = Wk; bias = bk; out = g_k; scale = 1.0f;   break;
        default: W = Wv; bias = bv; out = g_v; scale = 1.0f;   break;
    }

    const int tx = threadIdx.x, ty = threadIdx.y;
    const int tid = ty * 16 + tx;
    const int row0 = blockIdx.x * BM;
    const int lr = tid >> 3;   // 0..31
    const int lc = tid & 7;    // 0..7

    float acc[4][4] = {};

    for (int k0 = 0; k0 < DMODEL; k0 += 32) {
        // Load X chunk [64 rows x 32 k], store transposed Xt[k][m]
        #pragma unroll
        for (int p = 0; p < 2; p++) {
            int rr = lr + p * 32;
            float4 v = *(const float4*)&x[(row0 + rr) * DMODEL + k0 + lc * 4];
            Xt[lc * 4 + 0][rr] = v.x;
            Xt[lc * 4 + 1][rr] = v.y;
            Xt[lc * 4 + 2][rr] = v.z;
            Xt[lc * 4 + 3][rr] = v.w;
        }
        // Load W chunk [32 k x 64 cols] row-major
        {
            float4 w0 = *(const float4*)&W[(k0 + lr) * DHEAD + lc * 4];
            float4 w1 = *(const float4*)&W[(k0 + lr) * DHEAD + (lc + 8) * 4];
            *(float4*)&Ws[lr][lc * 4]       = w0;
            *(float4*)&Ws[lr][(lc + 8) * 4] = w1;
        }
        __syncthreads();

        #pragma unroll
        for (int kk = 0; kk < 32; kk++) {
            float4 a4 = *(const float4*)&Xt[kk][ty * 4];
            float4 b4 = *(const float4*)&Ws[kk][tx * 4];
            float a[4] = {a4.x, a4.y, a4.z, a4.w};
            float b[4] = {b4.x, b4.y, b4.z, b4.w};
            #pragma unroll
            for (int i = 0; i < 4; i++)
                #pragma unroll
                for (int j = 0; j < 4; j++)
                    acc[i][j] = fmaf(a[i], b[j], acc[i][j]);
        }
        __syncthreads();
    }

    float4 b4 = *(const float4*)&bias[tx * 4];
    float bb[4] = {b4.x, b4.y, b4.z, b4.w};
    #pragma unroll
    for (int i = 0; i < 4; i++) {
        int row = row0 + ty * 4 + i;
        float4 r;
        r.x = (acc[i][0] + bb[0]) * scale;
        r.y = (acc[i][1] + bb[1]) * scale;
        r.z = (acc[i][2] + bb[2]) * scale;
        r.w = (acc[i][3] + bb[3]) * scale;
        *(float4*)&out[row * DHEAD + tx * 4] = r;
    }
}

// ---------------------------------------------------------------------------
// Flash attention, fp32. One block = 64 queries of one batch; loops over all
// 4096 keys in tiles of 64. Online softmax with 16-lane shfl reductions.
// Q/K stored d-major in smem so both GEMMs do within-row float4 reads
// (conflict-free). Mask applied post-softmax (-inf on P), denominator
// unmasked — faithful to the reference.
// ---------------------------------------------------------------------------
__global__ __launch_bounds__(256)
void attn_kernel(const int* __restrict__ mask, float* __restrict__ out) {
    extern __shared__ float sm[];
    float* Qt = sm;                         // [DHEAD][BM]  (d-major)
    float* Kt = sm + DHEAD * BM;            // [DHEAD][BN]  (d-major)
    float* Vs = Kt + DHEAD * BN;            // [BN][DHEAD]  (row-major)
    float* Ps = Vs + BN * DHEAD;            // [BM][BN]

    const int b  = blockIdx.y;
    const int q0 = blockIdx.x * BM;
    const int tx = threadIdx.x, ty = threadIdx.y;
    const int tid = ty * 16 + tx;

    const float* qg  = g_q + (b * S_LEN + q0) * DHEAD;
    const float* kg  = g_k + b * S_LEN * DHEAD;
    const float* vg  = g_v + b * S_LEN * DHEAD;
    const int*   mkb = mask + b * S_LEN;

    // Load Q tile, transposed to Qt[d][m]
    {
        int r = tid >> 2;   // 0..63 (query row)
        int c = tid & 3;    // chunk of 16 d-values
        #pragma unroll
        for (int p = 0; p < 4; p++) {
            int d = c * 16 + p * 4;
            float4 v = *(const float4*)&qg[r * DHEAD + d];
            Qt[(d + 0) * BM + r] = v.x;
            Qt[(d + 1) * BM + r] = v.y;
            Qt[(d + 2) * BM + r] = v.z;
            Qt[(d + 3) * BM + r] = v.w;
        }
    }

    float o[4][4] = {};
    float mrow[4] = {-CUDART_INF_F, -CUDART_INF_F, -CUDART_INF_F, -CUDART_INF_F};
    float lrow[4] = {};

    for (int n0 = 0; n0 < S_LEN; n0 += BN) {
        __syncthreads();  // prior GEMM2 done before K/V overwrite (also covers Q load, iter 0)

        // Load K tile transposed (Kt[d][n]) and V tile row-major (Vs[n][d])
        {
            int r = tid >> 2;
            int c = tid & 3;
            #pragma unroll
            for (int p = 0; p < 4; p++) {
                int d = c * 16 + p * 4;
                float4 v = *(const float4*)&kg[(n0 + r) * DHEAD + d];
                Kt[(d + 0) * BN + r] = v.x;
                Kt[(d + 1) * BN + r] = v.y;
                Kt[(d + 2) * BN + r] = v.z;
                Kt[(d + 3) * BN + r] = v.w;
                float4 w = *(const float4*)&vg[(n0 + r) * DHEAD + d];
                *(float4*)&Vs[r * DHEAD + d] = w;
            }
        }
        __syncthreads();

        // GEMM1: S = Q K^T  (q pre-scaled by 0.125)
        float s[4][4] = {};
        #pragma unroll
        for (int d = 0; d < DHEAD; d++) {
            float4 a4 = *(const float4*)&Qt[d * BM + ty * 4];
            float4 k4 = *(const float4*)&Kt[d * BN + tx * 4];
            float a[4] = {a4.x, a4.y, a4.z, a4.w};
            float kv[4] = {k4.x, k4.y, k4.z, k4.w};
            #pragma unroll
            for (int i = 0; i < 4; i++)
                #pragma unroll
                for (int j = 0; j < 4; j++)
                    s[i][j] = fmaf(a[i], kv[j], s[i][j]);
        }

        // Online softmax (rows owned by 16-lane groups; xor-shfl reductions)
        #pragma unroll
        for (int i = 0; i < 4; i++) {
            float rm = fmaxf(fmaxf(s[i][0], s[i][1]), fmaxf(s[i][2], s[i][3]));
            rm = fmaxf(rm, __shfl_xor_sync(0xffffffffu, rm, 1));
            rm = fmaxf(rm, __shfl_xor_sync(0xffffffffu, rm, 2));
            rm = fmaxf(rm, __shfl_xor_sync(0xffffffffu, rm, 4));
            rm = fmaxf(rm, __shfl_xor_sync(0xffffffffu, rm, 8));
            float mn = fmaxf(mrow[i], rm);
            float al = __expf(mrow[i] - mn);   // exp(-inf)=0 handles first iter
            #pragma unroll
            for (int j = 0; j < 4; j++) s[i][j] = __expf(s[i][j] - mn);
            float rs = (s[i][0] + s[i][1]) + (s[i][2] + s[i][3]);
            rs += __shfl_xor_sync(0xffffffffu, rs, 1);
            rs += __shfl_xor_sync(0xffffffffu, rs, 2);
            rs += __shfl_xor_sync(0xffffffffu, rs, 4);
            rs += __shfl_xor_sync(0xffffffffu, rs, 8);
            lrow[i] = lrow[i] * al + rs;       // denominator: UNMASKED (ref masks after softmax)
            mrow[i] = mn;
            #pragma unroll
            for (int j = 0; j < 4; j++) o[i][j] *= al;
        }

        // Apply post-softmax mask and stage P in smem
        int4 mk4 = *(const int4*)&mkb[n0 + tx * 4];
        #pragma unroll
        for (int i = 0; i < 4; i++) {
            float4 pr;
            pr.x = (mk4.x == 0) ? -CUDART_INF_F : s[i][0];
            pr.y = (mk4.y == 0) ? -CUDART_INF_F : s[i][1];
            pr.z = (mk4.z == 0) ? -CUDART_INF_F : s[i][2];
            pr.w = (mk4.w == 0) ? -CUDART_INF_F : s[i][3];
            *(float4*)&Ps[(ty * 4 + i) * BN + tx * 4] = pr;
        }
        __syncthreads();

        // GEMM2: O += P V
        #pragma unroll
        for (int n4 = 0; n4 < BN; n4 += 4) {
            float4 pa[4];
            #pragma unroll
            for (int i = 0; i < 4; i++)
                pa[i] = *(const float4*)&Ps[(ty * 4 + i) * BN + n4];
            #pragma unroll
            for (int u = 0; u < 4; u++) {
                float4 v4 = *(const float4*)&Vs[(n4 + u) * DHEAD + tx * 4];
                float vv[4] = {v4.x, v4.y, v4.z, v4.w};
                #pragma unroll
                for (int i = 0; i < 4; i++) {
                    float pv = ((const float*)&pa[i])[u];
                    #pragma unroll
                    for (int j = 0; j < 4; j++)
                        o[i][j] = fmaf(pv, vv[j], o[i][j]);
                }
            }
        }
    }

    // Epilogue: normalize and write
    #pragma unroll
    for (int i = 0; i < 4; i++) {
        float inv = 1.0f / lrow[i];
        float4 r;
        r.x = o[i][0] * inv;
        r.y = o[i][1] * inv;
        r.z = o[i][2] * inv;
        r.w = o[i][3] * inv;
        *(float4*)&out[(b * S_LEN + q0 + ty * 4 + i) * DHEAD + tx * 4] = r;
    }
}

// ---------------------------------------------------------------------------
// Launch: inputs (metadata order): x, mask, Wq, bq, Wk, bk, Wv, bv
// ---------------------------------------------------------------------------
extern "C" void kernel_launch(void* const* d_in, const int* in_sizes, int n_in,
                              void* d_out, int out_size) {
    const float* x    = (const float*)d_in[0];
    const int*   mask = (const int*)  d_in[1];
    const float* Wq   = (const float*)d_in[2];
    const float* bq   = (const float*)d_in[3];
    const float* Wk   = (const float*)d_in[4];
    const float* bk   = (const float*)d_in[5];
    const float* Wv   = (const float*)d_in[6];
    const float* bv   = (const float*)d_in[7];
    float* out = (float*)d_out;

    dim3 blk(16, 16);
    qkv_kernel<<<dim3(NROWS / BM, 3), blk>>>(x, Wq, bq, Wk, bk, Wv, bv);

    const int attn_smem = 4 * BM * BN * (int)sizeof(float);  // 64 KB
    cudaFuncSetAttribute(attn_kernel, cudaFuncAttributeMaxDynamicSharedMemorySize, attn_smem);
    attn_kernel<<<dim3(S_LEN / BM, BATCH), blk, attn_smem>>>(mask, out);
}